// round 14
// baseline (speedup 1.0000x reference)
#include <cuda_runtime.h>
#include <cuda_fp16.h>
#include <cstdint>

#define NN   50000
#define EE   800000
#define HD   128
#define OUTD 64
#define LN_EPS 1e-5f

// -------- device scratch --------
__device__ __align__(16) __half g_fth[NN * HD];  // per-layer features, fp16
__device__ __align__(16) float g_h1[NN * HD];
__device__ __align__(16) float g_h2[NN * HD];
__device__ __align__(16) float g_el[NN * 4];
__device__ __align__(16) float g_er[NN * 4];
__device__ __align__(16) float g_att[EE * 4];   // fallback only (deg > 128)
__device__ __align__(16) int2 g_edge[EE];       // (src, float-bits ew), CSR order
__device__ int g_rank[EE];
__device__ int g_cnt[NN];                        // zero at load; re-zeroed by k_mega1
__device__ int g_off[NN];

// clean 8-byte fp16x4 load type (members accessed directly; never address-cast)
struct __align__(8) h2x2 { __half2 a, b; };

// ---------------------------- CSR build ------------------------------------
__global__ void k_hist(const int* __restrict__ dst) {
    int e = blockIdx.x * blockDim.x + threadIdx.x;
    if (e < EE) g_rank[e] = atomicAdd(&g_cnt[dst[e]], 1);
}

__global__ void k_scan_all() {
    __shared__ int sh[1024];
    int t = threadIdx.x;
    int sum = 0;
    for (int i = t; i < NN; i += 1024) sum += g_cnt[i];
    sh[t] = sum;
    __syncthreads();
    for (int off = 1; off < 1024; off <<= 1) {
        int add = (t >= off) ? sh[t - off] : 0;
        __syncthreads();
        sh[t] += add;
        __syncthreads();
    }
    int base = sh[t] - sum;
    for (int i = t; i < NN; i += 1024) {
        int c = g_cnt[i];
        g_off[i] = base;
        base += c;
    }
}

__global__ void k_scatter(const int* __restrict__ src, const int* __restrict__ dst,
                          const float* __restrict__ ew) {
    int e = blockIdx.x * blockDim.x + threadIdx.x;
    if (e < EE) {
        int p = g_off[dst[e]] + g_rank[e];
        g_edge[p] = make_int2(src[e], __float_as_int(ew[e]));
    }
}

// ---- fp16 tensor-core GEMM (m16n8k16), fp16 output, fused el/er epilogue ----
// C[NN, MC] = A[NN,128] @ B[128, MC].  8 warps, warp tile 16x64.
// A staged [BM][20] uint (half2 pairs along k, 32 k per stage).
// B staged TRANSPOSED [MC][20] uint (half2 pairs along k) -> 1 LDS.32 per frag.
// Stride 20 uints puts the 8-row x 4-lane frag pattern on 32 distinct banks.
template <int MC>
__global__ void k_gemm_fp16(const float* __restrict__ A, const float* __restrict__ B,
                            __half* __restrict__ C, const float* __restrict__ al,
                            const float* __restrict__ ar) {
    constexpr int BM = (MC == 128) ? 64 : 128;
    constexpr int WCOLS = MC / 64;
    constexpr int WROWS = 8 / WCOLS;
    __shared__ uint32_t As2[BM][20];
    __shared__ uint32_t Bs2[MC][20];

    int tid = threadIdx.x;
    int wid = tid >> 5, lane = tid & 31;
    int wr = wid % WROWS, wc = wid / WROWS;
    int row0 = blockIdx.x * BM;
    int lg = lane & 3;            // thread in quad
    int lr = lane >> 2;           // quad id

    float c[8][4];
#pragma unroll
    for (int t = 0; t < 8; t++)
#pragma unroll
        for (int i = 0; i < 4; i++) c[t][i] = 0.f;

    for (int kt = 0; kt < 128; kt += 32) {
        // stage A: BM rows x 32 k, half2-packed
#pragma unroll
        for (int i = 0; i < BM / 32; i++) {
            int idx = tid + i * 256;
            int r = idx >> 3, cc = idx & 7;
            int gr = row0 + r;
            float4 v = make_float4(0.f, 0.f, 0.f, 0.f);
            if (gr < NN) v = *(const float4*)&A[gr * 128 + kt + cc * 4];
            *(__half2*)&As2[r][cc * 2] = __floats2half2_rn(v.x, v.y);
            *(__half2*)&As2[r][cc * 2 + 1] = __floats2half2_rn(v.z, v.w);
        }
        // stage B transposed: global [k][n] -> smem [n][k/2]
#pragma unroll
        for (int i = 0; i < MC / 32; i++) {
            int idx = tid + i * 256;
            int r = idx / (MC / 4), cq = idx % (MC / 4);
            float4 v = *(const float4*)&B[(kt + r) * MC + cq * 4];
            __half* bh = (__half*)Bs2;
            bh[(cq * 4 + 0) * 40 + r] = __float2half_rn(v.x);
            bh[(cq * 4 + 1) * 40 + r] = __float2half_rn(v.y);
            bh[(cq * 4 + 2) * 40 + r] = __float2half_rn(v.z);
            bh[(cq * 4 + 3) * 40 + r] = __float2half_rn(v.w);
        }
        __syncthreads();
#pragma unroll
        for (int ks = 0; ks < 2; ks++) {           // two K=16 steps per 32-k tile
            int k0 = ks * 8;                        // in half2 units
            int ar_ = wr * 16 + lr;
            uint32_t a0 = As2[ar_][k0 + lg];
            uint32_t a1 = As2[ar_ + 8][k0 + lg];
            uint32_t a2 = As2[ar_][k0 + lg + 4];
            uint32_t a3 = As2[ar_ + 8][k0 + lg + 4];
#pragma unroll
            for (int t = 0; t < 8; t++) {
                int n0 = wc * 64 + t * 8 + lr;
                uint32_t b0 = Bs2[n0][k0 + lg];
                uint32_t b1 = Bs2[n0][k0 + lg + 4];
                asm volatile(
                    "mma.sync.aligned.m16n8k16.row.col.f32.f16.f16.f32 "
                    "{%0,%1,%2,%3}, {%4,%5,%6,%7}, {%8,%9}, {%0,%1,%2,%3};"
                    : "+f"(c[t][0]), "+f"(c[t][1]), "+f"(c[t][2]), "+f"(c[t][3])
                    : "r"(a0), "r"(a1), "r"(a2), "r"(a3), "r"(b0), "r"(b1));
            }
        }
        __syncthreads();
    }

    int rbase = row0 + wr * 16 + lr;
    // ---- writeout C (fp16) ----
#pragma unroll
    for (int t = 0; t < 8; t++) {
        int n0 = wc * 64 + t * 8 + 2 * lg;
        if (rbase < NN)
            *(__half2*)&C[rbase * MC + n0] = __floats2half2_rn(c[t][0], c[t][1]);
        if (rbase + 8 < NN)
            *(__half2*)&C[(rbase + 8) * MC + n0] = __floats2half2_rn(c[t][2], c[t][3]);
    }

    // ---- fused el/er epilogue ----
    if (MC == 128) {
        float pel[2][2] = {{0.f, 0.f}, {0.f, 0.f}};
        float per[2][2] = {{0.f, 0.f}, {0.f, 0.f}};
#pragma unroll
        for (int t = 0; t < 8; t++) {
            int n0 = wc * 64 + t * 8 + 2 * lg;
            int hl = t >> 2;
            float a0 = al[n0], a1 = al[n0 + 1];
            float r0 = ar[n0], r1 = ar[n0 + 1];
            pel[0][hl] += c[t][0] * a0 + c[t][1] * a1;
            per[0][hl] += c[t][0] * r0 + c[t][1] * r1;
            pel[1][hl] += c[t][2] * a0 + c[t][3] * a1;
            per[1][hl] += c[t][2] * r0 + c[t][3] * r1;
        }
#pragma unroll
        for (int off = 1; off < 4; off <<= 1) {
#pragma unroll
            for (int rr = 0; rr < 2; rr++)
#pragma unroll
                for (int hh = 0; hh < 2; hh++) {
                    pel[rr][hh] += __shfl_xor_sync(0xffffffffu, pel[rr][hh], off);
                    per[rr][hh] += __shfl_xor_sync(0xffffffffu, per[rr][hh], off);
                }
        }
        if (lg == 0) {
            int h0 = wc * 2;
            if (rbase < NN) {
                g_el[rbase * 4 + h0] = pel[0][0];
                g_el[rbase * 4 + h0 + 1] = pel[0][1];
                g_er[rbase * 4 + h0] = per[0][0];
                g_er[rbase * 4 + h0 + 1] = per[0][1];
            }
            if (rbase + 8 < NN) {
                g_el[(rbase + 8) * 4 + h0] = pel[1][0];
                g_el[(rbase + 8) * 4 + h0 + 1] = pel[1][1];
                g_er[(rbase + 8) * 4 + h0] = per[1][0];
                g_er[(rbase + 8) * 4 + h0 + 1] = per[1][1];
            }
        }
    } else {
        float pel[2] = {0.f, 0.f}, per[2] = {0.f, 0.f};
#pragma unroll
        for (int t = 0; t < 8; t++) {
            int n0 = t * 8 + 2 * lg;
            float a0 = al[n0], a1 = al[n0 + 1];
            float r0 = ar[n0], r1 = ar[n0 + 1];
            pel[0] += c[t][0] * a0 + c[t][1] * a1;
            per[0] += c[t][0] * r0 + c[t][1] * r1;
            pel[1] += c[t][2] * a0 + c[t][3] * a1;
            per[1] += c[t][2] * r0 + c[t][3] * r1;
        }
#pragma unroll
        for (int off = 1; off < 4; off <<= 1) {
#pragma unroll
            for (int rr = 0; rr < 2; rr++) {
                pel[rr] += __shfl_xor_sync(0xffffffffu, pel[rr], off);
                per[rr] += __shfl_xor_sync(0xffffffffu, per[rr], off);
            }
        }
        if (lg == 0) {
            if (rbase < NN) { g_el[rbase] = pel[0]; g_er[rbase] = per[0]; }
            if (rbase + 8 < NN) { g_el[rbase + 8] = pel[1]; g_er[rbase + 8] = per[1]; }
        }
    }
}

__device__ __forceinline__ float4 lrelu4(float4 v) {
    v.x = v.x > 0.f ? v.x : 0.2f * v.x;
    v.y = v.y > 0.f ? v.y : 0.2f * v.y;
    v.z = v.z > 0.f ? v.z : 0.2f * v.z;
    v.w = v.w > 0.f ? v.w : 0.2f * v.w;
    return v;
}

// ---- mega kernel, hidden layers (H=4,D=32) ----------------------------------
__global__ void k_mega4(const __half* __restrict__ ft, const float* __restrict__ lam,
                        const float* __restrict__ resid, const float* __restrict__ gamma,
                        const float* __restrict__ beta, float* __restrict__ out) {
    __shared__ float s_att[8][512];
    __shared__ int s_src[8][128];
    int wslot = threadIdx.x >> 5;
    int w = (blockIdx.x * blockDim.x + threadIdx.x) >> 5;
    int lane = threadIdx.x & 31;
    if (w >= NN) return;
    int deg = g_cnt[w];
    int st = g_off[w];
    float lamv = lam[0];
    float4 er4 = *(const float4*)&g_er[w * 4];
    int hl = lane >> 3;

    float4 acc = make_float4(0.f, 0.f, 0.f, 0.f);

    if (deg <= 128) {
        float4 sc[4];
        float4 mx = make_float4(-1e30f, -1e30f, -1e30f, -1e30f);
#pragma unroll
        for (int k = 0; k < 4; k++) {
            int j = lane + 32 * k;
            if (j < deg) {
                int2 ed = g_edge[st + j];
                int s = ed.x;
                s_src[wslot][j] = s;
                float wb = lamv * __int_as_float(ed.y);
                float4 elv = *(const float4*)&g_el[s * 4];
                float4 v;
                v.x = elv.x + er4.x + wb; v.y = elv.y + er4.y + wb;
                v.z = elv.z + er4.z + wb; v.w = elv.w + er4.w + wb;
                v = lrelu4(v);
                sc[k] = v;
                mx.x = fmaxf(mx.x, v.x); mx.y = fmaxf(mx.y, v.y);
                mx.z = fmaxf(mx.z, v.z); mx.w = fmaxf(mx.w, v.w);
            }
        }
#pragma unroll
        for (int off = 16; off > 0; off >>= 1) {
            mx.x = fmaxf(mx.x, __shfl_xor_sync(0xffffffffu, mx.x, off));
            mx.y = fmaxf(mx.y, __shfl_xor_sync(0xffffffffu, mx.y, off));
            mx.z = fmaxf(mx.z, __shfl_xor_sync(0xffffffffu, mx.z, off));
            mx.w = fmaxf(mx.w, __shfl_xor_sync(0xffffffffu, mx.w, off));
        }
        float4 sm = make_float4(0.f, 0.f, 0.f, 0.f);
#pragma unroll
        for (int k = 0; k < 4; k++) {
            int j = lane + 32 * k;
            if (j < deg) {
                sc[k].x = __expf(sc[k].x - mx.x);
                sc[k].y = __expf(sc[k].y - mx.y);
                sc[k].z = __expf(sc[k].z - mx.z);
                sc[k].w = __expf(sc[k].w - mx.w);
                sm.x += sc[k].x; sm.y += sc[k].y; sm.z += sc[k].z; sm.w += sc[k].w;
            }
        }
#pragma unroll
        for (int off = 16; off > 0; off >>= 1) {
            sm.x += __shfl_xor_sync(0xffffffffu, sm.x, off);
            sm.y += __shfl_xor_sync(0xffffffffu, sm.y, off);
            sm.z += __shfl_xor_sync(0xffffffffu, sm.z, off);
            sm.w += __shfl_xor_sync(0xffffffffu, sm.w, off);
        }
        float rh = (hl == 0) ? sm.x : (hl == 1) ? sm.y : (hl == 2) ? sm.z : sm.w;
        float rinv = 1.f / rh;
#pragma unroll
        for (int k = 0; k < 4; k++) {
            int j = lane + 32 * k;
            if (j < deg) *(float4*)&s_att[wslot][j * 4] = sc[k];
        }
        __syncwarp();
#pragma unroll 2
        for (int j = 0; j < deg; j++) {
            float a = s_att[wslot][j * 4 + hl] * rinv;
            int s = s_src[wslot][j];
            h2x2 v = *(const h2x2*)&ft[s * 128 + lane * 4];
            float2 f0 = __half22float2(v.a);
            float2 f1 = __half22float2(v.b);
            acc.x = fmaf(f0.x, a, acc.x);
            acc.y = fmaf(f0.y, a, acc.y);
            acc.z = fmaf(f1.x, a, acc.z);
            acc.w = fmaf(f1.y, a, acc.w);
        }
    } else {
        float4 mx = make_float4(-1e30f, -1e30f, -1e30f, -1e30f);
        for (int j = lane; j < deg; j += 32) {
            int p = st + j;
            int2 ed = g_edge[p];
            float wb = lamv * __int_as_float(ed.y);
            float4 elv = *(const float4*)&g_el[ed.x * 4];
            float4 v;
            v.x = elv.x + er4.x + wb; v.y = elv.y + er4.y + wb;
            v.z = elv.z + er4.z + wb; v.w = elv.w + er4.w + wb;
            v = lrelu4(v);
            *(float4*)&g_att[p * 4] = v;
            mx.x = fmaxf(mx.x, v.x); mx.y = fmaxf(mx.y, v.y);
            mx.z = fmaxf(mx.z, v.z); mx.w = fmaxf(mx.w, v.w);
        }
#pragma unroll
        for (int off = 16; off > 0; off >>= 1) {
            mx.x = fmaxf(mx.x, __shfl_xor_sync(0xffffffffu, mx.x, off));
            mx.y = fmaxf(mx.y, __shfl_xor_sync(0xffffffffu, mx.y, off));
            mx.z = fmaxf(mx.z, __shfl_xor_sync(0xffffffffu, mx.z, off));
            mx.w = fmaxf(mx.w, __shfl_xor_sync(0xffffffffu, mx.w, off));
        }
        float4 sm = make_float4(0.f, 0.f, 0.f, 0.f);
        for (int j = lane; j < deg; j += 32) {
            int p = st + j;
            float4 v = *(const float4*)&g_att[p * 4];
            v.x = __expf(v.x - mx.x); v.y = __expf(v.y - mx.y);
            v.z = __expf(v.z - mx.z); v.w = __expf(v.w - mx.w);
            *(float4*)&g_att[p * 4] = v;
            sm.x += v.x; sm.y += v.y; sm.z += v.z; sm.w += v.w;
        }
#pragma unroll
        for (int off = 16; off > 0; off >>= 1) {
            sm.x += __shfl_xor_sync(0xffffffffu, sm.x, off);
            sm.y += __shfl_xor_sync(0xffffffffu, sm.y, off);
            sm.z += __shfl_xor_sync(0xffffffffu, sm.z, off);
            sm.w += __shfl_xor_sync(0xffffffffu, sm.w, off);
        }
        float rh = (hl == 0) ? sm.x : (hl == 1) ? sm.y : (hl == 2) ? sm.z : sm.w;
        float rinv = 1.f / rh;
        __syncwarp();
        for (int j = 0; j < deg; j++) {
            int p = st + j;
            int s = g_edge[p].x;
            float a = g_att[p * 4 + hl] * rinv;
            h2x2 v = *(const h2x2*)&ft[s * 128 + lane * 4];
            float2 f0 = __half22float2(v.a);
            float2 f1 = __half22float2(v.b);
            acc.x = fmaf(f0.x, a, acc.x);
            acc.y = fmaf(f0.y, a, acc.y);
            acc.z = fmaf(f1.x, a, acc.z);
            acc.w = fmaf(f1.y, a, acc.w);
        }
    }

    acc.x = acc.x > 0.f ? acc.x : (__expf(acc.x) - 1.f);
    acc.y = acc.y > 0.f ? acc.y : (__expf(acc.y) - 1.f);
    acc.z = acc.z > 0.f ? acc.z : (__expf(acc.z) - 1.f);
    acc.w = acc.w > 0.f ? acc.w : (__expf(acc.w) - 1.f);
    float s1 = acc.x + acc.y + acc.z + acc.w;
    float s2 = acc.x * acc.x + acc.y * acc.y + acc.z * acc.z + acc.w * acc.w;
#pragma unroll
    for (int off = 16; off > 0; off >>= 1) {
        s1 += __shfl_xor_sync(0xffffffffu, s1, off);
        s2 += __shfl_xor_sync(0xffffffffu, s2, off);
    }
    float mu = s1 * (1.f / 128.f);
    float var = s2 * (1.f / 128.f) - mu * mu;
    float rs = rsqrtf(fmaxf(var, 0.f) + LN_EPS);
    float4 g4 = *(const float4*)&gamma[lane * 4];
    float4 b4 = *(const float4*)&beta[lane * 4];
    float4 r4 = *(const float4*)&resid[w * 128 + lane * 4];
    float4 o;
    o.x = (acc.x - mu) * rs * g4.x + b4.x + r4.x;
    o.y = (acc.y - mu) * rs * g4.y + b4.y + r4.y;
    o.z = (acc.z - mu) * rs * g4.z + b4.z + r4.z;
    o.w = (acc.w - mu) * rs * g4.w + b4.w + r4.w;
    *(float4*)&out[w * 128 + lane * 4] = o;
}

// ---- mega kernel, final layer (H=1, OUT=64); also re-zeros g_cnt ------------
__global__ void k_mega1(const __half* __restrict__ ft, const float* __restrict__ lam,
                        float* __restrict__ out, float* __restrict__ out2) {
    __shared__ float s_att[8][128];
    __shared__ int s_src[8][128];
    int wslot = threadIdx.x >> 5;
    int w = (blockIdx.x * blockDim.x + threadIdx.x) >> 5;
    int lane = threadIdx.x & 31;
    if (w >= NN) return;
    int deg = g_cnt[w];
    int st = g_off[w];
    float lamv = lam[0];
    float er = g_er[w];

    float2 acc = make_float2(0.f, 0.f);

    if (deg <= 128) {
        float sc[4];
        float mx = -1e30f;
#pragma unroll
        for (int k = 0; k < 4; k++) {
            int j = lane + 32 * k;
            if (j < deg) {
                int2 ed = g_edge[st + j];
                int s = ed.x;
                s_src[wslot][j] = s;
                float v = g_el[s] + er + lamv * __int_as_float(ed.y);
                v = v > 0.f ? v : 0.2f * v;
                sc[k] = v;
                mx = fmaxf(mx, v);
            }
        }
#pragma unroll
        for (int off = 16; off > 0; off >>= 1)
            mx = fmaxf(mx, __shfl_xor_sync(0xffffffffu, mx, off));
        float sm = 0.f;
#pragma unroll
        for (int k = 0; k < 4; k++) {
            int j = lane + 32 * k;
            if (j < deg) { sc[k] = __expf(sc[k] - mx); sm += sc[k]; }
        }
#pragma unroll
        for (int off = 16; off > 0; off >>= 1)
            sm += __shfl_xor_sync(0xffffffffu, sm, off);
        float rinv = 1.f / sm;
#pragma unroll
        for (int k = 0; k < 4; k++) {
            int j = lane + 32 * k;
            if (j < deg) s_att[wslot][j] = sc[k];
        }
        __syncwarp();
#pragma unroll 2
        for (int j = 0; j < deg; j++) {
            float a = s_att[wslot][j] * rinv;
            int s = s_src[wslot][j];
            float2 f = __half22float2(*(const __half2*)&ft[s * 64 + lane * 2]);
            acc.x = fmaf(f.x, a, acc.x);
            acc.y = fmaf(f.y, a, acc.y);
        }
    } else {
        float mx = -1e30f;
        for (int j = lane; j < deg; j += 32) {
            int p = st + j;
            int2 ed = g_edge[p];
            float v = g_el[ed.x] + er + lamv * __int_as_float(ed.y);
            v = v > 0.f ? v : 0.2f * v;
            g_att[p] = v;
            mx = fmaxf(mx, v);
        }
#pragma unroll
        for (int off = 16; off > 0; off >>= 1)
            mx = fmaxf(mx, __shfl_xor_sync(0xffffffffu, mx, off));
        float sm = 0.f;
        for (int j = lane; j < deg; j += 32) {
            int p = st + j;
            float v = __expf(g_att[p] - mx);
            g_att[p] = v;
            sm += v;
        }
#pragma unroll
        for (int off = 16; off > 0; off >>= 1)
            sm += __shfl_xor_sync(0xffffffffu, sm, off);
        float rinv = 1.f / sm;
        __syncwarp();
        for (int j = 0; j < deg; j++) {
            int p = st + j;
            int s = g_edge[p].x;
            float a = g_att[p] * rinv;
            float2 f = __half22float2(*(const __half2*)&ft[s * 64 + lane * 2]);
            acc.x = fmaf(f.x, a, acc.x);
            acc.y = fmaf(f.y, a, acc.y);
        }
    }
    *(float2*)&out[w * 64 + lane * 2] = acc;
    if (out2) *(float2*)&out2[w * 64 + lane * 2] = acc;
    if (lane == 0) g_cnt[w] = 0;   // leave counters clean for the next call
}

// ------------------------------- launch --------------------------------------
extern "C" void kernel_launch(void* const* d_in, const int* in_sizes, int n_in,
                              void* d_out, int out_size) {
    (void)in_sizes; (void)n_in;
    const float* feat = (const float*)d_in[0];
    const float* ew   = (const float*)d_in[1];
    const int*   src  = (const int*)d_in[2];
    const int*   dst  = (const int*)d_in[3];
    const float* W0   = (const float*)d_in[4];
    const float* al0  = (const float*)d_in[5];
    const float* ar0  = (const float*)d_in[6];
    const float* lam0 = (const float*)d_in[7];
    const float* W1   = (const float*)d_in[8];
    const float* al1  = (const float*)d_in[9];
    const float* ar1  = (const float*)d_in[10];
    const float* lam1 = (const float*)d_in[11];
    const float* W2   = (const float*)d_in[12];
    const float* al2  = (const float*)d_in[13];
    const float* ar2  = (const float*)d_in[14];
    const float* lam2 = (const float*)d_in[15];
    const float* g0   = (const float*)d_in[16];
    const float* b0   = (const float*)d_in[17];
    const float* g1   = (const float*)d_in[18];
    const float* b1   = (const float*)d_in[19];

    float* out = (float*)d_out;
    float* out2 = (out_size >= 2 * NN * OUTD) ? out + NN * OUTD : nullptr;

    __half* fthp = nullptr;
    float *h1p = nullptr, *h2p = nullptr;
    cudaGetSymbolAddress((void**)&fthp, g_fth);
    cudaGetSymbolAddress((void**)&h1p, g_h1);
    cudaGetSymbolAddress((void**)&h2p, g_h2);

    const int eb = (EE + 255) / 256;
    const int nwb = (NN + 7) / 8;
    const int g128b = (NN + 63) / 64;
    const int g64b = (NN + 127) / 128;

    // CSR by dst (3 kernels; g_cnt pre-zeroed by module load / previous call)
    k_hist<<<eb, 256>>>(dst);
    k_scan_all<<<1, 1024>>>();
    k_scatter<<<eb, 256>>>(src, dst, ew);

    // layer 0
    k_gemm_fp16<128><<<g128b, 256>>>(feat, W0, fthp, al0, ar0);
    k_mega4<<<nwb, 256>>>(fthp, lam0, feat, g0, b0, h1p);

    // layer 1
    k_gemm_fp16<128><<<g128b, 256>>>(h1p, W1, fthp, al1, ar1);
    k_mega4<<<nwb, 256>>>(fthp, lam1, h1p, g1, b1, h2p);

    // layer 2
    k_gemm_fp16<64><<<g64b, 256>>>(h2p, W2, fthp, al2, ar2);
    k_mega1<<<nwb, 256>>>(fthp, lam2, out, out2);
}

// round 15
// speedup vs baseline: 1.1359x; 1.1359x over previous
#include <cuda_runtime.h>
#include <cuda_fp16.h>
#include <cstdint>

#define NN   50000
#define EE   800000
#define HD   128
#define OUTD 64
#define LN_EPS 1e-5f

// -------- device scratch --------
__device__ __align__(16) __half g_fth[NN * HD];  // per-layer features, fp16
__device__ __align__(16) float g_h1[NN * HD];
__device__ __align__(16) float g_h2[NN * HD];
__device__ __align__(16) float g_el[NN * 4];
__device__ __align__(16) float g_er[NN * 4];
__device__ __align__(16) float g_att[EE * 4];   // fallback only (deg > 128)
__device__ __align__(16) int2 g_edge[EE];       // (src, float-bits ew), CSR order
__device__ int g_rank[EE];
__device__ int g_cnt[NN];                        // zero at load; re-zeroed by k_mega1
__device__ int g_off[NN];

// clean 8-byte fp16x4 load type (members accessed directly; never address-cast)
struct __align__(8) h2x2 { __half2 a, b; };

// ---------------------------- CSR build ------------------------------------
__global__ void k_hist(const int* __restrict__ dst) {
    int e = blockIdx.x * blockDim.x + threadIdx.x;
    if (e < EE) g_rank[e] = atomicAdd(&g_cnt[dst[e]], 1);
}

__global__ void k_scan_all() {
    __shared__ int sh[1024];
    int t = threadIdx.x;
    int sum = 0;
    for (int i = t; i < NN; i += 1024) sum += g_cnt[i];
    sh[t] = sum;
    __syncthreads();
    for (int off = 1; off < 1024; off <<= 1) {
        int add = (t >= off) ? sh[t - off] : 0;
        __syncthreads();
        sh[t] += add;
        __syncthreads();
    }
    int base = sh[t] - sum;
    for (int i = t; i < NN; i += 1024) {
        int c = g_cnt[i];
        g_off[i] = base;
        base += c;
    }
}

__global__ void k_scatter(const int* __restrict__ src, const int* __restrict__ dst,
                          const float* __restrict__ ew) {
    int e = blockIdx.x * blockDim.x + threadIdx.x;
    if (e < EE) {
        int p = g_off[dst[e]] + g_rank[e];
        g_edge[p] = make_int2(src[e], __float_as_int(ew[e]));
    }
}

// --------------------------- tf32 helpers ------------------------------------
__device__ __forceinline__ uint32_t f2tf32(float x) {
    uint32_t r;
    asm("cvt.rna.tf32.f32 %0, %1;" : "=r"(r) : "f"(x));
    return r;
}

// ------- tf32 tensor-core GEMM, fp16 output, fused el/er epilogue ------------
template <int MC>
__global__ void k_gemm_tf32(const float* __restrict__ A, const float* __restrict__ B,
                            __half* __restrict__ C, const float* __restrict__ al,
                            const float* __restrict__ ar) {
    constexpr int BM = (MC == 128) ? 64 : 128;
    constexpr int BSTR = MC + 8;
    constexpr int WCOLS = MC / 64;
    constexpr int WROWS = 8 / WCOLS;
    __shared__ uint32_t As[BM][36];
    __shared__ uint32_t Bs[32][BSTR];

    int tid = threadIdx.x;
    int wid = tid >> 5, lane = tid & 31;
    int wr = wid % WROWS, wc = wid / WROWS;
    int row0 = blockIdx.x * BM;

    float c[8][4];
#pragma unroll
    for (int t = 0; t < 8; t++)
#pragma unroll
        for (int i = 0; i < 4; i++) c[t][i] = 0.f;

    for (int kt = 0; kt < 128; kt += 32) {
#pragma unroll
        for (int i = 0; i < BM / 32; i++) {
            int idx = tid + i * 256;
            int r = idx >> 3, cc = idx & 7;
            int gr = row0 + r;
            float4 v = make_float4(0.f, 0.f, 0.f, 0.f);
            if (gr < NN) v = *(const float4*)&A[gr * 128 + kt + cc * 4];
            As[r][cc * 4 + 0] = f2tf32(v.x);
            As[r][cc * 4 + 1] = f2tf32(v.y);
            As[r][cc * 4 + 2] = f2tf32(v.z);
            As[r][cc * 4 + 3] = f2tf32(v.w);
        }
#pragma unroll
        for (int i = 0; i < MC / 32; i++) {
            int idx = tid + i * 256;
            int r = idx / (MC / 4), cc = idx % (MC / 4);
            float4 v = *(const float4*)&B[(kt + r) * MC + cc * 4];
            Bs[r][cc * 4 + 0] = f2tf32(v.x);
            Bs[r][cc * 4 + 1] = f2tf32(v.y);
            Bs[r][cc * 4 + 2] = f2tf32(v.z);
            Bs[r][cc * 4 + 3] = f2tf32(v.w);
        }
        __syncthreads();
#pragma unroll
        for (int ks = 0; ks < 4; ks++) {
            int k0 = ks * 8;
            int ar_ = wr * 16 + (lane >> 2);
            int ac = k0 + (lane & 3);
            uint32_t a0 = As[ar_][ac];
            uint32_t a1 = As[ar_ + 8][ac];
            uint32_t a2 = As[ar_][ac + 4];
            uint32_t a3 = As[ar_ + 8][ac + 4];
#pragma unroll
            for (int t = 0; t < 8; t++) {
                int n0 = wc * 64 + t * 8 + (lane >> 2);
                uint32_t b0 = Bs[k0 + (lane & 3)][n0];
                uint32_t b1 = Bs[k0 + (lane & 3) + 4][n0];
                asm volatile(
                    "mma.sync.aligned.m16n8k8.row.col.f32.tf32.tf32.f32 "
                    "{%0,%1,%2,%3}, {%4,%5,%6,%7}, {%8,%9}, {%0,%1,%2,%3};"
                    : "+f"(c[t][0]), "+f"(c[t][1]), "+f"(c[t][2]), "+f"(c[t][3])
                    : "r"(a0), "r"(a1), "r"(a2), "r"(a3), "r"(b0), "r"(b1));
            }
        }
        __syncthreads();
    }

    int rbase = row0 + wr * 16 + (lane >> 2);
#pragma unroll
    for (int t = 0; t < 8; t++) {
        int n0 = wc * 64 + t * 8 + 2 * (lane & 3);
        if (rbase < NN)
            *(__half2*)&C[rbase * MC + n0] = __floats2half2_rn(c[t][0], c[t][1]);
        if (rbase + 8 < NN)
            *(__half2*)&C[(rbase + 8) * MC + n0] = __floats2half2_rn(c[t][2], c[t][3]);
    }

    // ---- fused el/er epilogue ----
    if (MC == 128) {
        float pel[2][2] = {{0.f, 0.f}, {0.f, 0.f}};
        float per[2][2] = {{0.f, 0.f}, {0.f, 0.f}};
#pragma unroll
        for (int t = 0; t < 8; t++) {
            int n0 = wc * 64 + t * 8 + 2 * (lane & 3);
            int hl = t >> 2;
            float a0 = al[n0], a1 = al[n0 + 1];
            float r0 = ar[n0], r1 = ar[n0 + 1];
            pel[0][hl] += c[t][0] * a0 + c[t][1] * a1;
            per[0][hl] += c[t][0] * r0 + c[t][1] * r1;
            pel[1][hl] += c[t][2] * a0 + c[t][3] * a1;
            per[1][hl] += c[t][2] * r0 + c[t][3] * r1;
        }
#pragma unroll
        for (int off = 1; off < 4; off <<= 1) {
#pragma unroll
            for (int rr = 0; rr < 2; rr++)
#pragma unroll
                for (int hh = 0; hh < 2; hh++) {
                    pel[rr][hh] += __shfl_xor_sync(0xffffffffu, pel[rr][hh], off);
                    per[rr][hh] += __shfl_xor_sync(0xffffffffu, per[rr][hh], off);
                }
        }
        if ((lane & 3) == 0) {
            int h0 = wc * 2;
            if (rbase < NN) {
                g_el[rbase * 4 + h0] = pel[0][0];
                g_el[rbase * 4 + h0 + 1] = pel[0][1];
                g_er[rbase * 4 + h0] = per[0][0];
                g_er[rbase * 4 + h0 + 1] = per[0][1];
            }
            if (rbase + 8 < NN) {
                g_el[(rbase + 8) * 4 + h0] = pel[1][0];
                g_el[(rbase + 8) * 4 + h0 + 1] = pel[1][1];
                g_er[(rbase + 8) * 4 + h0] = per[1][0];
                g_er[(rbase + 8) * 4 + h0 + 1] = per[1][1];
            }
        }
    } else {
        float pel[2] = {0.f, 0.f}, per[2] = {0.f, 0.f};
#pragma unroll
        for (int t = 0; t < 8; t++) {
            int n0 = t * 8 + 2 * (lane & 3);
            float a0 = al[n0], a1 = al[n0 + 1];
            float r0 = ar[n0], r1 = ar[n0 + 1];
            pel[0] += c[t][0] * a0 + c[t][1] * a1;
            per[0] += c[t][0] * r0 + c[t][1] * r1;
            pel[1] += c[t][2] * a0 + c[t][3] * a1;
            per[1] += c[t][2] * r0 + c[t][3] * r1;
        }
#pragma unroll
        for (int off = 1; off < 4; off <<= 1) {
#pragma unroll
            for (int rr = 0; rr < 2; rr++) {
                pel[rr] += __shfl_xor_sync(0xffffffffu, pel[rr], off);
                per[rr] += __shfl_xor_sync(0xffffffffu, per[rr], off);
            }
        }
        if ((lane & 3) == 0) {
            if (rbase < NN) { g_el[rbase] = pel[0]; g_er[rbase] = per[0]; }
            if (rbase + 8 < NN) { g_el[rbase + 8] = pel[1]; g_er[rbase + 8] = per[1]; }
        }
    }
}

__device__ __forceinline__ float4 lrelu4(float4 v) {
    v.x = v.x > 0.f ? v.x : 0.2f * v.x;
    v.y = v.y > 0.f ? v.y : 0.2f * v.y;
    v.z = v.z > 0.f ? v.z : 0.2f * v.z;
    v.w = v.w > 0.f ? v.w : 0.2f * v.w;
    return v;
}

// ---- mega kernel, hidden layers (H=4,D=32) ----------------------------------
__global__ void k_mega4(const __half* __restrict__ ft, const float* __restrict__ lam,
                        const float* __restrict__ resid, const float* __restrict__ gamma,
                        const float* __restrict__ beta, float* __restrict__ out) {
    __shared__ float s_att[8][512];
    __shared__ int s_src[8][128];
    int wslot = threadIdx.x >> 5;
    int w = (blockIdx.x * blockDim.x + threadIdx.x) >> 5;
    int lane = threadIdx.x & 31;
    if (w >= NN) return;
    int deg = g_cnt[w];
    int st = g_off[w];
    float lamv = lam[0];
    float4 er4 = *(const float4*)&g_er[w * 4];
    int hl = lane >> 3;

    float4 acc = make_float4(0.f, 0.f, 0.f, 0.f);

    if (deg <= 128) {
        float4 sc[4];
        float4 mx = make_float4(-1e30f, -1e30f, -1e30f, -1e30f);
#pragma unroll
        for (int k = 0; k < 4; k++) {
            int j = lane + 32 * k;
            if (j < deg) {
                int2 ed = g_edge[st + j];
                int s = ed.x;
                s_src[wslot][j] = s;
                float wb = lamv * __int_as_float(ed.y);
                float4 elv = *(const float4*)&g_el[s * 4];
                float4 v;
                v.x = elv.x + er4.x + wb; v.y = elv.y + er4.y + wb;
                v.z = elv.z + er4.z + wb; v.w = elv.w + er4.w + wb;
                v = lrelu4(v);
                sc[k] = v;
                mx.x = fmaxf(mx.x, v.x); mx.y = fmaxf(mx.y, v.y);
                mx.z = fmaxf(mx.z, v.z); mx.w = fmaxf(mx.w, v.w);
            }
        }
#pragma unroll
        for (int off = 16; off > 0; off >>= 1) {
            mx.x = fmaxf(mx.x, __shfl_xor_sync(0xffffffffu, mx.x, off));
            mx.y = fmaxf(mx.y, __shfl_xor_sync(0xffffffffu, mx.y, off));
            mx.z = fmaxf(mx.z, __shfl_xor_sync(0xffffffffu, mx.z, off));
            mx.w = fmaxf(mx.w, __shfl_xor_sync(0xffffffffu, mx.w, off));
        }
        float4 sm = make_float4(0.f, 0.f, 0.f, 0.f);
#pragma unroll
        for (int k = 0; k < 4; k++) {
            int j = lane + 32 * k;
            if (j < deg) {
                sc[k].x = __expf(sc[k].x - mx.x);
                sc[k].y = __expf(sc[k].y - mx.y);
                sc[k].z = __expf(sc[k].z - mx.z);
                sc[k].w = __expf(sc[k].w - mx.w);
                sm.x += sc[k].x; sm.y += sc[k].y; sm.z += sc[k].z; sm.w += sc[k].w;
            }
        }
#pragma unroll
        for (int off = 16; off > 0; off >>= 1) {
            sm.x += __shfl_xor_sync(0xffffffffu, sm.x, off);
            sm.y += __shfl_xor_sync(0xffffffffu, sm.y, off);
            sm.z += __shfl_xor_sync(0xffffffffu, sm.z, off);
            sm.w += __shfl_xor_sync(0xffffffffu, sm.w, off);
        }
        float rh = (hl == 0) ? sm.x : (hl == 1) ? sm.y : (hl == 2) ? sm.z : sm.w;
        float rinv = 1.f / rh;
#pragma unroll
        for (int k = 0; k < 4; k++) {
            int j = lane + 32 * k;
            if (j < deg) *(float4*)&s_att[wslot][j * 4] = sc[k];
        }
        __syncwarp();
#pragma unroll 2
        for (int j = 0; j < deg; j++) {
            float a = s_att[wslot][j * 4 + hl] * rinv;
            int s = s_src[wslot][j];
            h2x2 v = *(const h2x2*)&ft[s * 128 + lane * 4];
            float2 f0 = __half22float2(v.a);
            float2 f1 = __half22float2(v.b);
            acc.x = fmaf(f0.x, a, acc.x);
            acc.y = fmaf(f0.y, a, acc.y);
            acc.z = fmaf(f1.x, a, acc.z);
            acc.w = fmaf(f1.y, a, acc.w);
        }
    } else {
        float4 mx = make_float4(-1e30f, -1e30f, -1e30f, -1e30f);
        for (int j = lane; j < deg; j += 32) {
            int p = st + j;
            int2 ed = g_edge[p];
            float wb = lamv * __int_as_float(ed.y);
            float4 elv = *(const float4*)&g_el[ed.x * 4];
            float4 v;
            v.x = elv.x + er4.x + wb; v.y = elv.y + er4.y + wb;
            v.z = elv.z + er4.z + wb; v.w = elv.w + er4.w + wb;
            v = lrelu4(v);
            *(float4*)&g_att[p * 4] = v;
            mx.x = fmaxf(mx.x, v.x); mx.y = fmaxf(mx.y, v.y);
            mx.z = fmaxf(mx.z, v.z); mx.w = fmaxf(mx.w, v.w);
        }
#pragma unroll
        for (int off = 16; off > 0; off >>= 1) {
            mx.x = fmaxf(mx.x, __shfl_xor_sync(0xffffffffu, mx.x, off));
            mx.y = fmaxf(mx.y, __shfl_xor_sync(0xffffffffu, mx.y, off));
            mx.z = fmaxf(mx.z, __shfl_xor_sync(0xffffffffu, mx.z, off));
            mx.w = fmaxf(mx.w, __shfl_xor_sync(0xffffffffu, mx.w, off));
        }
        float4 sm = make_float4(0.f, 0.f, 0.f, 0.f);
        for (int j = lane; j < deg; j += 32) {
            int p = st + j;
            float4 v = *(const float4*)&g_att[p * 4];
            v.x = __expf(v.x - mx.x); v.y = __expf(v.y - mx.y);
            v.z = __expf(v.z - mx.z); v.w = __expf(v.w - mx.w);
            *(float4*)&g_att[p * 4] = v;
            sm.x += v.x; sm.y += v.y; sm.z += v.z; sm.w += v.w;
        }
#pragma unroll
        for (int off = 16; off > 0; off >>= 1) {
            sm.x += __shfl_xor_sync(0xffffffffu, sm.x, off);
            sm.y += __shfl_xor_sync(0xffffffffu, sm.y, off);
            sm.z += __shfl_xor_sync(0xffffffffu, sm.z, off);
            sm.w += __shfl_xor_sync(0xffffffffu, sm.w, off);
        }
        float rh = (hl == 0) ? sm.x : (hl == 1) ? sm.y : (hl == 2) ? sm.z : sm.w;
        float rinv = 1.f / rh;
        __syncwarp();
        for (int j = 0; j < deg; j++) {
            int p = st + j;
            int s = g_edge[p].x;
            float a = g_att[p * 4 + hl] * rinv;
            h2x2 v = *(const h2x2*)&ft[s * 128 + lane * 4];
            float2 f0 = __half22float2(v.a);
            float2 f1 = __half22float2(v.b);
            acc.x = fmaf(f0.x, a, acc.x);
            acc.y = fmaf(f0.y, a, acc.y);
            acc.z = fmaf(f1.x, a, acc.z);
            acc.w = fmaf(f1.y, a, acc.w);
        }
    }

    acc.x = acc.x > 0.f ? acc.x : (__expf(acc.x) - 1.f);
    acc.y = acc.y > 0.f ? acc.y : (__expf(acc.y) - 1.f);
    acc.z = acc.z > 0.f ? acc.z : (__expf(acc.z) - 1.f);
    acc.w = acc.w > 0.f ? acc.w : (__expf(acc.w) - 1.f);
    float s1 = acc.x + acc.y + acc.z + acc.w;
    float s2 = acc.x * acc.x + acc.y * acc.y + acc.z * acc.z + acc.w * acc.w;
#pragma unroll
    for (int off = 16; off > 0; off >>= 1) {
        s1 += __shfl_xor_sync(0xffffffffu, s1, off);
        s2 += __shfl_xor_sync(0xffffffffu, s2, off);
    }
    float mu = s1 * (1.f / 128.f);
    float var = s2 * (1.f / 128.f) - mu * mu;
    float rs = rsqrtf(fmaxf(var, 0.f) + LN_EPS);
    float4 g4 = *(const float4*)&gamma[lane * 4];
    float4 b4 = *(const float4*)&beta[lane * 4];
    float4 r4 = *(const float4*)&resid[w * 128 + lane * 4];
    float4 o;
    o.x = (acc.x - mu) * rs * g4.x + b4.x + r4.x;
    o.y = (acc.y - mu) * rs * g4.y + b4.y + r4.y;
    o.z = (acc.z - mu) * rs * g4.z + b4.z + r4.z;
    o.w = (acc.w - mu) * rs * g4.w + b4.w + r4.w;
    *(float4*)&out[w * 128 + lane * 4] = o;
}

// ---- mega kernel, final layer (H=1, OUT=64); also re-zeros g_cnt ------------
__global__ void k_mega1(const __half* __restrict__ ft, const float* __restrict__ lam,
                        float* __restrict__ out, float* __restrict__ out2) {
    __shared__ float s_att[8][128];
    __shared__ int s_src[8][128];
    int wslot = threadIdx.x >> 5;
    int w = (blockIdx.x * blockDim.x + threadIdx.x) >> 5;
    int lane = threadIdx.x & 31;
    if (w >= NN) return;
    int deg = g_cnt[w];
    int st = g_off[w];
    float lamv = lam[0];
    float er = g_er[w];

    float2 acc = make_float2(0.f, 0.f);

    if (deg <= 128) {
        float sc[4];
        float mx = -1e30f;
#pragma unroll
        for (int k = 0; k < 4; k++) {
            int j = lane + 32 * k;
            if (j < deg) {
                int2 ed = g_edge[st + j];
                int s = ed.x;
                s_src[wslot][j] = s;
                float v = g_el[s] + er + lamv * __int_as_float(ed.y);
                v = v > 0.f ? v : 0.2f * v;
                sc[k] = v;
                mx = fmaxf(mx, v);
            }
        }
#pragma unroll
        for (int off = 16; off > 0; off >>= 1)
            mx = fmaxf(mx, __shfl_xor_sync(0xffffffffu, mx, off));
        float sm = 0.f;
#pragma unroll
        for (int k = 0; k < 4; k++) {
            int j = lane + 32 * k;
            if (j < deg) { sc[k] = __expf(sc[k] - mx); sm += sc[k]; }
        }
#pragma unroll
        for (int off = 16; off > 0; off >>= 1)
            sm += __shfl_xor_sync(0xffffffffu, sm, off);
        float rinv = 1.f / sm;
#pragma unroll
        for (int k = 0; k < 4; k++) {
            int j = lane + 32 * k;
            if (j < deg) s_att[wslot][j] = sc[k];
        }
        __syncwarp();
#pragma unroll 2
        for (int j = 0; j < deg; j++) {
            float a = s_att[wslot][j] * rinv;
            int s = s_src[wslot][j];
            float2 f = __half22float2(*(const __half2*)&ft[s * 64 + lane * 2]);
            acc.x = fmaf(f.x, a, acc.x);
            acc.y = fmaf(f.y, a, acc.y);
        }
    } else {
        float mx = -1e30f;
        for (int j = lane; j < deg; j += 32) {
            int p = st + j;
            int2 ed = g_edge[p];
            float v = g_el[ed.x] + er + lamv * __int_as_float(ed.y);
            v = v > 0.f ? v : 0.2f * v;
            g_att[p] = v;
            mx = fmaxf(mx, v);
        }
#pragma unroll
        for (int off = 16; off > 0; off >>= 1)
            mx = fmaxf(mx, __shfl_xor_sync(0xffffffffu, mx, off));
        float sm = 0.f;
        for (int j = lane; j < deg; j += 32) {
            int p = st + j;
            float v = __expf(g_att[p] - mx);
            g_att[p] = v;
            sm += v;
        }
#pragma unroll
        for (int off = 16; off > 0; off >>= 1)
            sm += __shfl_xor_sync(0xffffffffu, sm, off);
        float rinv = 1.f / sm;
        __syncwarp();
        for (int j = 0; j < deg; j++) {
            int p = st + j;
            int s = g_edge[p].x;
            float a = g_att[p] * rinv;
            float2 f = __half22float2(*(const __half2*)&ft[s * 64 + lane * 2]);
            acc.x = fmaf(f.x, a, acc.x);
            acc.y = fmaf(f.y, a, acc.y);
        }
    }
    *(float2*)&out[w * 64 + lane * 2] = acc;
    if (out2) *(float2*)&out2[w * 64 + lane * 2] = acc;
    if (lane == 0) g_cnt[w] = 0;   // leave counters clean for the next call
}

// ------------------------------- launch --------------------------------------
extern "C" void kernel_launch(void* const* d_in, const int* in_sizes, int n_in,
                              void* d_out, int out_size) {
    (void)in_sizes; (void)n_in;
    const float* feat = (const float*)d_in[0];
    const float* ew   = (const float*)d_in[1];
    const int*   src  = (const int*)d_in[2];
    const int*   dst  = (const int*)d_in[3];
    const float* W0   = (const float*)d_in[4];
    const float* al0  = (const float*)d_in[5];
    const float* ar0  = (const float*)d_in[6];
    const float* lam0 = (const float*)d_in[7];
    const float* W1   = (const float*)d_in[8];
    const float* al1  = (const float*)d_in[9];
    const float* ar1  = (const float*)d_in[10];
    const float* lam1 = (const float*)d_in[11];
    const float* W2   = (const float*)d_in[12];
    const float* al2  = (const float*)d_in[13];
    const float* ar2  = (const float*)d_in[14];
    const float* lam2 = (const float*)d_in[15];
    const float* g0   = (const float*)d_in[16];
    const float* b0   = (const float*)d_in[17];
    const float* g1   = (const float*)d_in[18];
    const float* b1   = (const float*)d_in[19];

    float* out = (float*)d_out;
    float* out2 = (out_size >= 2 * NN * OUTD) ? out + NN * OUTD : nullptr;

    __half* fthp = nullptr;
    float *h1p = nullptr, *h2p = nullptr;
    cudaGetSymbolAddress((void**)&fthp, g_fth);
    cudaGetSymbolAddress((void**)&h1p, g_h1);
    cudaGetSymbolAddress((void**)&h2p, g_h2);

    const int eb = (EE + 255) / 256;
    const int nwb = (NN + 7) / 8;
    const int g128b = (NN + 63) / 64;
    const int g64b = (NN + 127) / 128;

    // CSR by dst (3 kernels; g_cnt pre-zeroed by module load / previous call)
    k_hist<<<eb, 256>>>(dst);
    k_scan_all<<<1, 1024>>>();
    k_scatter<<<eb, 256>>>(src, dst, ew);

    // layer 0
    k_gemm_tf32<128><<<g128b, 256>>>(feat, W0, fthp, al0, ar0);
    k_mega4<<<nwb, 256>>>(fthp, lam0, feat, g0, b0, h1p);

    // layer 1
    k_gemm_tf32<128><<<g128b, 256>>>(h1p, W1, fthp, al1, ar1);
    k_mega4<<<nwb, 256>>>(fthp, lam1, h1p, g1, b1, h2p);

    // layer 2
    k_gemm_tf32<64><<<g64b, 256>>>(h2p, W2, fthp, al2, ar2);
    k_mega1<<<nwb, 256>>>(fthp, lam2, out, out2);
}

// round 17
// speedup vs baseline: 1.2749x; 1.1224x over previous
#include <cuda_runtime.h>
#include <cuda_fp16.h>
#include <cstdint>

#define NN   50000
#define EE   800000
#define HD   128
#define OUTD 64
#define LN_EPS 1e-5f

// -------- device scratch --------
__device__ __align__(16) __half g_fth[NN * HD];  // per-layer features, fp16
__device__ __align__(16) float g_h1[NN * HD];
__device__ __align__(16) float g_h2[NN * HD];
__device__ __align__(16) float g_el[NN * 4];
__device__ __align__(16) float g_er[NN * 4];
__device__ __align__(16) float g_att[EE * 4];   // fallback only (deg > 128)
__device__ __align__(16) int2 g_edge[EE];       // (src, float-bits ew), CSR order
__device__ int g_rank[EE];
__device__ int g_cnt[NN];                        // zero at load; re-zeroed by k_mega1
__device__ int g_off[NN];

struct __align__(8) h2x2 { __half2 a, b; };

// ---------------------------- CSR build ------------------------------------
__global__ void k_hist(const int* __restrict__ dst) {
    int e = blockIdx.x * blockDim.x + threadIdx.x;
    if (e < EE) g_rank[e] = atomicAdd(&g_cnt[dst[e]], 1);
}

__global__ void k_scan_all() {
    __shared__ int sh[1024];
    int t = threadIdx.x;
    int sum = 0;
    for (int i = t; i < NN; i += 1024) sum += g_cnt[i];
    sh[t] = sum;
    __syncthreads();
    for (int off = 1; off < 1024; off <<= 1) {
        int add = (t >= off) ? sh[t - off] : 0;
        __syncthreads();
        sh[t] += add;
        __syncthreads();
    }
    int base = sh[t] - sum;
    for (int i = t; i < NN; i += 1024) {
        int c = g_cnt[i];
        g_off[i] = base;
        base += c;
    }
}

__global__ void k_scatter(const int* __restrict__ src, const int* __restrict__ dst,
                          const float* __restrict__ ew) {
    int e = blockIdx.x * blockDim.x + threadIdx.x;
    if (e < EE) {
        int p = g_off[dst[e]] + g_rank[e];
        g_edge[p] = make_int2(src[e], __float_as_int(ew[e]));
    }
}

// -------- helpers ------------------------------------------------------------
__device__ __forceinline__ void cpa16(uint32_t dst, const void* src) {
    asm volatile("cp.async.ca.shared.global [%0], [%1], 16;" :: "r"(dst), "l"(src));
}
__device__ __forceinline__ void cpa16z(uint32_t dst, const void* src, int szbytes) {
    asm volatile("cp.async.ca.shared.global [%0], [%1], 16, %2;"
                 :: "r"(dst), "l"(src), "r"(szbytes));
}
__device__ __forceinline__ uint32_t cvt32(uint32_t bits) {   // RNA fp32->tf32
    uint32_t r;
    asm("cvt.rna.tf32.f32 %0, %1;" : "=r"(r) : "r"(bits));
    return r;
}

// -- tf32 GEMM, cp.async double-buffered, in-register RNA cvt, fused el/er ----
// C[NN, MC] = A[NN,128] @ B[128, MC].  8 warps, warp tile 16x64.
template <int MC>
__global__ void k_gemm_tf32(const float* __restrict__ A, const float* __restrict__ B,
                            __half* __restrict__ C, const float* __restrict__ al,
                            const float* __restrict__ ar) {
    constexpr int BM = (MC == 128) ? 64 : 128;
    constexpr int BSTR = MC + 8;
    constexpr int ASZ = BM * 36;
    constexpr int BSZ = 32 * BSTR;
    constexpr int WCOLS = MC / 64;
    constexpr int WROWS = 8 / WCOLS;
    extern __shared__ uint32_t sm[];
    uint32_t* As_ = sm;
    uint32_t* Bs_ = sm + 2 * ASZ;
    uint32_t smb = (uint32_t)__cvta_generic_to_shared(sm);

    int tid = threadIdx.x;
    int wid = tid >> 5, lane = tid & 31;
    int wr = wid % WROWS, wc = wid / WROWS;
    int row0 = blockIdx.x * BM;
    int lq = lane & 3, lr = lane >> 2;

    float c[8][4];
#pragma unroll
    for (int t = 0; t < 8; t++)
#pragma unroll
        for (int i = 0; i < 4; i++) c[t][i] = 0.f;

    auto stage = [&](int kt, int buf) {
#pragma unroll
        for (int i = 0; i < BM / 32; i++) {
            int idx = tid + i * 256;
            int r = idx >> 3, cc = idx & 7;
            int gr = row0 + r;
            uint32_t dst = smb + (buf * ASZ + r * 36 + cc * 4) * 4;
            cpa16z(dst, &A[(size_t)(gr < NN ? gr : 0) * 128 + kt + cc * 4],
                   gr < NN ? 16 : 0);
        }
#pragma unroll
        for (int i = 0; i < MC / 32; i++) {
            int idx = tid + i * 256;
            int r = idx / (MC / 4), cc = idx % (MC / 4);
            uint32_t dst = smb + (2 * ASZ + buf * BSZ + r * BSTR + cc * 4) * 4;
            cpa16(dst, &B[(kt + r) * MC + cc * 4]);
        }
        asm volatile("cp.async.commit_group;");
    };

    stage(0, 0);
#pragma unroll
    for (int t4 = 0; t4 < 4; t4++) {
        if (t4 < 3) {
            stage((t4 + 1) * 32, (t4 + 1) & 1);
            asm volatile("cp.async.wait_group 1;");
        } else {
            asm volatile("cp.async.wait_group 0;");
        }
        __syncthreads();
        const uint32_t* Ab = As_ + (t4 & 1) * ASZ;
        const uint32_t* Bb = Bs_ + (t4 & 1) * BSZ;
#pragma unroll
        for (int ks = 0; ks < 4; ks++) {
            int k0 = ks * 8;
            int ar_ = wr * 16 + lr;
            uint32_t a0 = cvt32(Ab[ar_ * 36 + k0 + lq]);
            uint32_t a1 = cvt32(Ab[(ar_ + 8) * 36 + k0 + lq]);
            uint32_t a2 = cvt32(Ab[ar_ * 36 + k0 + lq + 4]);
            uint32_t a3 = cvt32(Ab[(ar_ + 8) * 36 + k0 + lq + 4]);
#pragma unroll
            for (int t = 0; t < 8; t++) {
                int n0 = wc * 64 + t * 8 + lr;
                uint32_t b0 = cvt32(Bb[(k0 + lq) * BSTR + n0]);
                uint32_t b1 = cvt32(Bb[(k0 + lq + 4) * BSTR + n0]);
                asm volatile(
                    "mma.sync.aligned.m16n8k8.row.col.f32.tf32.tf32.f32 "
                    "{%0,%1,%2,%3}, {%4,%5,%6,%7}, {%8,%9}, {%0,%1,%2,%3};"
                    : "+f"(c[t][0]), "+f"(c[t][1]), "+f"(c[t][2]), "+f"(c[t][3])
                    : "r"(a0), "r"(a1), "r"(a2), "r"(a3), "r"(b0), "r"(b1));
            }
        }
        __syncthreads();
    }

    int rbase = row0 + wr * 16 + lr;
#pragma unroll
    for (int t = 0; t < 8; t++) {
        int n0 = wc * 64 + t * 8 + 2 * lq;
        if (rbase < NN)
            *(__half2*)&C[rbase * MC + n0] = __floats2half2_rn(c[t][0], c[t][1]);
        if (rbase + 8 < NN)
            *(__half2*)&C[(rbase + 8) * MC + n0] = __floats2half2_rn(c[t][2], c[t][3]);
    }

    // ---- fused el/er epilogue ----
    if (MC == 128) {
        float pel[2][2] = {{0.f, 0.f}, {0.f, 0.f}};
        float per[2][2] = {{0.f, 0.f}, {0.f, 0.f}};
#pragma unroll
        for (int t = 0; t < 8; t++) {
            int n0 = wc * 64 + t * 8 + 2 * lq;
            int hl = t >> 2;
            float a0 = al[n0], a1 = al[n0 + 1];
            float r0 = ar[n0], r1 = ar[n0 + 1];
            pel[0][hl] += c[t][0] * a0 + c[t][1] * a1;
            per[0][hl] += c[t][0] * r0 + c[t][1] * r1;
            pel[1][hl] += c[t][2] * a0 + c[t][3] * a1;
            per[1][hl] += c[t][2] * r0 + c[t][3] * r1;
        }
#pragma unroll
        for (int off = 1; off < 4; off <<= 1) {
#pragma unroll
            for (int rr = 0; rr < 2; rr++)
#pragma unroll
                for (int hh = 0; hh < 2; hh++) {
                    pel[rr][hh] += __shfl_xor_sync(0xffffffffu, pel[rr][hh], off);
                    per[rr][hh] += __shfl_xor_sync(0xffffffffu, per[rr][hh], off);
                }
        }
        if (lq == 0) {
            int h0 = wc * 2;
            if (rbase < NN) {
                g_el[rbase * 4 + h0] = pel[0][0];
                g_el[rbase * 4 + h0 + 1] = pel[0][1];
                g_er[rbase * 4 + h0] = per[0][0];
                g_er[rbase * 4 + h0 + 1] = per[0][1];
            }
            if (rbase + 8 < NN) {
                g_el[(rbase + 8) * 4 + h0] = pel[1][0];
                g_el[(rbase + 8) * 4 + h0 + 1] = pel[1][1];
                g_er[(rbase + 8) * 4 + h0] = per[1][0];
                g_er[(rbase + 8) * 4 + h0 + 1] = per[1][1];
            }
        }
    } else {
        float pel[2] = {0.f, 0.f}, per[2] = {0.f, 0.f};
#pragma unroll
        for (int t = 0; t < 8; t++) {
            int n0 = t * 8 + 2 * lq;
            float a0 = al[n0], a1 = al[n0 + 1];
            float r0 = ar[n0], r1 = ar[n0 + 1];
            pel[0] += c[t][0] * a0 + c[t][1] * a1;
            per[0] += c[t][0] * r0 + c[t][1] * r1;
            pel[1] += c[t][2] * a0 + c[t][3] * a1;
            per[1] += c[t][2] * r0 + c[t][3] * r1;
        }
#pragma unroll
        for (int off = 1; off < 4; off <<= 1) {
#pragma unroll
            for (int rr = 0; rr < 2; rr++) {
                pel[rr] += __shfl_xor_sync(0xffffffffu, pel[rr], off);
                per[rr] += __shfl_xor_sync(0xffffffffu, per[rr], off);
            }
        }
        if (lq == 0) {
            if (rbase < NN) { g_el[rbase] = pel[0]; g_er[rbase] = per[0]; }
            if (rbase + 8 < NN) { g_el[rbase + 8] = pel[1]; g_er[rbase + 8] = per[1]; }
        }
    }
}

__device__ __forceinline__ float4 lrelu4(float4 v) {
    v.x = v.x > 0.f ? v.x : 0.2f * v.x;
    v.y = v.y > 0.f ? v.y : 0.2f * v.y;
    v.z = v.z > 0.f ? v.z : 0.2f * v.z;
    v.w = v.w > 0.f ? v.w : 0.2f * v.w;
    return v;
}

// ---- mega kernel, hidden layers (H=4,D=32) ----------------------------------
__global__ void k_mega4(const __half* __restrict__ ft, const float* __restrict__ lam,
                        const float* __restrict__ resid, const float* __restrict__ gamma,
                        const float* __restrict__ beta, float* __restrict__ out) {
    __shared__ float s_att[8][512];
    __shared__ int s_src[8][128];
    int wslot = threadIdx.x >> 5;
    int w = (blockIdx.x * blockDim.x + threadIdx.x) >> 5;
    int lane = threadIdx.x & 31;
    if (w >= NN) return;
    int deg = g_cnt[w];
    int st = g_off[w];
    float lamv = lam[0];
    float4 er4 = *(const float4*)&g_er[w * 4];
    int hl = lane >> 3;

    float4 acc = make_float4(0.f, 0.f, 0.f, 0.f);

    if (deg <= 128) {
        float4 sc[4];
        float4 mx = make_float4(-1e30f, -1e30f, -1e30f, -1e30f);
#pragma unroll
        for (int k = 0; k < 4; k++) {
            int j = lane + 32 * k;
            if (j < deg) {
                int2 ed = g_edge[st + j];
                int s = ed.x;
                s_src[wslot][j] = s;
                float wb = lamv * __int_as_float(ed.y);
                float4 elv = *(const float4*)&g_el[s * 4];
                float4 v;
                v.x = elv.x + er4.x + wb; v.y = elv.y + er4.y + wb;
                v.z = elv.z + er4.z + wb; v.w = elv.w + er4.w + wb;
                v = lrelu4(v);
                sc[k] = v;
                mx.x = fmaxf(mx.x, v.x); mx.y = fmaxf(mx.y, v.y);
                mx.z = fmaxf(mx.z, v.z); mx.w = fmaxf(mx.w, v.w);
            }
        }
#pragma unroll
        for (int off = 16; off > 0; off >>= 1) {
            mx.x = fmaxf(mx.x, __shfl_xor_sync(0xffffffffu, mx.x, off));
            mx.y = fmaxf(mx.y, __shfl_xor_sync(0xffffffffu, mx.y, off));
            mx.z = fmaxf(mx.z, __shfl_xor_sync(0xffffffffu, mx.z, off));
            mx.w = fmaxf(mx.w, __shfl_xor_sync(0xffffffffu, mx.w, off));
        }
        float4 sm = make_float4(0.f, 0.f, 0.f, 0.f);
#pragma unroll
        for (int k = 0; k < 4; k++) {
            int j = lane + 32 * k;
            if (j < deg) {
                sc[k].x = __expf(sc[k].x - mx.x);
                sc[k].y = __expf(sc[k].y - mx.y);
                sc[k].z = __expf(sc[k].z - mx.z);
                sc[k].w = __expf(sc[k].w - mx.w);
                sm.x += sc[k].x; sm.y += sc[k].y; sm.z += sc[k].z; sm.w += sc[k].w;
            }
        }
#pragma unroll
        for (int off = 16; off > 0; off >>= 1) {
            sm.x += __shfl_xor_sync(0xffffffffu, sm.x, off);
            sm.y += __shfl_xor_sync(0xffffffffu, sm.y, off);
            sm.z += __shfl_xor_sync(0xffffffffu, sm.z, off);
            sm.w += __shfl_xor_sync(0xffffffffu, sm.w, off);
        }
        float rh = (hl == 0) ? sm.x : (hl == 1) ? sm.y : (hl == 2) ? sm.z : sm.w;
        float rinv = 1.f / rh;
#pragma unroll
        for (int k = 0; k < 4; k++) {
            int j = lane + 32 * k;
            if (j < deg) *(float4*)&s_att[wslot][j * 4] = sc[k];
        }
        __syncwarp();
#pragma unroll 4
        for (int j = 0; j < deg; j++) {
            float a = s_att[wslot][j * 4 + hl] * rinv;
            int s = s_src[wslot][j];
            h2x2 v = *(const h2x2*)&ft[s * 128 + lane * 4];
            float2 f0 = __half22float2(v.a);
            float2 f1 = __half22float2(v.b);
            acc.x = fmaf(f0.x, a, acc.x);
            acc.y = fmaf(f0.y, a, acc.y);
            acc.z = fmaf(f1.x, a, acc.z);
            acc.w = fmaf(f1.y, a, acc.w);
        }
    } else {
        float4 mx = make_float4(-1e30f, -1e30f, -1e30f, -1e30f);
        for (int j = lane; j < deg; j += 32) {
            int p = st + j;
            int2 ed = g_edge[p];
            float wb = lamv * __int_as_float(ed.y);
            float4 elv = *(const float4*)&g_el[ed.x * 4];
            float4 v;
            v.x = elv.x + er4.x + wb; v.y = elv.y + er4.y + wb;
            v.z = elv.z + er4.z + wb; v.w = elv.w + er4.w + wb;
            v = lrelu4(v);
            *(float4*)&g_att[p * 4] = v;
            mx.x = fmaxf(mx.x, v.x); mx.y = fmaxf(mx.y, v.y);
            mx.z = fmaxf(mx.z, v.z); mx.w = fmaxf(mx.w, v.w);
        }
#pragma unroll
        for (int off = 16; off > 0; off >>= 1) {
            mx.x = fmaxf(mx.x, __shfl_xor_sync(0xffffffffu, mx.x, off));
            mx.y = fmaxf(mx.y, __shfl_xor_sync(0xffffffffu, mx.y, off));
            mx.z = fmaxf(mx.z, __shfl_xor_sync(0xffffffffu, mx.z, off));
            mx.w = fmaxf(mx.w, __shfl_xor_sync(0xffffffffu, mx.w, off));
        }
        float4 sm = make_float4(0.f, 0.f, 0.f, 0.f);
        for (int j = lane; j < deg; j += 32) {
            int p = st + j;
            float4 v = *(const float4*)&g_att[p * 4];
            v.x = __expf(v.x - mx.x); v.y = __expf(v.y - mx.y);
            v.z = __expf(v.z - mx.z); v.w = __expf(v.w - mx.w);
            *(float4*)&g_att[p * 4] = v;
            sm.x += v.x; sm.y += v.y; sm.z += v.z; sm.w += v.w;
        }
#pragma unroll
        for (int off = 16; off > 0; off >>= 1) {
            sm.x += __shfl_xor_sync(0xffffffffu, sm.x, off);
            sm.y += __shfl_xor_sync(0xffffffffu, sm.y, off);
            sm.z += __shfl_xor_sync(0xffffffffu, sm.z, off);
            sm.w += __shfl_xor_sync(0xffffffffu, sm.w, off);
        }
        float rh = (hl == 0) ? sm.x : (hl == 1) ? sm.y : (hl == 2) ? sm.z : sm.w;
        float rinv = 1.f / rh;
        __syncwarp();
        for (int j = 0; j < deg; j++) {
            int p = st + j;
            int s = g_edge[p].x;
            float a = g_att[p * 4 + hl] * rinv;
            h2x2 v = *(const h2x2*)&ft[s * 128 + lane * 4];
            float2 f0 = __half22float2(v.a);
            float2 f1 = __half22float2(v.b);
            acc.x = fmaf(f0.x, a, acc.x);
            acc.y = fmaf(f0.y, a, acc.y);
            acc.z = fmaf(f1.x, a, acc.z);
            acc.w = fmaf(f1.y, a, acc.w);
        }
    }

    acc.x = acc.x > 0.f ? acc.x : (__expf(acc.x) - 1.f);
    acc.y = acc.y > 0.f ? acc.y : (__expf(acc.y) - 1.f);
    acc.z = acc.z > 0.f ? acc.z : (__expf(acc.z) - 1.f);
    acc.w = acc.w > 0.f ? acc.w : (__expf(acc.w) - 1.f);
    float s1 = acc.x + acc.y + acc.z + acc.w;
    float s2 = acc.x * acc.x + acc.y * acc.y + acc.z * acc.z + acc.w * acc.w;
#pragma unroll
    for (int off = 16; off > 0; off >>= 1) {
        s1 += __shfl_xor_sync(0xffffffffu, s1, off);
        s2 += __shfl_xor_sync(0xffffffffu, s2, off);
    }
    float mu = s1 * (1.f / 128.f);
    float var = s2 * (1.f / 128.f) - mu * mu;
    float rs = rsqrtf(fmaxf(var, 0.f) + LN_EPS);
    float4 g4 = *(const float4*)&gamma[lane * 4];
    float4 b4 = *(const float4*)&beta[lane * 4];
    float4 r4 = *(const float4*)&resid[w * 128 + lane * 4];
    float4 o;
    o.x = (acc.x - mu) * rs * g4.x + b4.x + r4.x;
    o.y = (acc.y - mu) * rs * g4.y + b4.y + r4.y;
    o.z = (acc.z - mu) * rs * g4.z + b4.z + r4.z;
    o.w = (acc.w - mu) * rs * g4.w + b4.w + r4.w;
    *(float4*)&out[w * 128 + lane * 4] = o;
}

// ---- mega kernel, final layer (H=1, OUT=64); also re-zeros g_cnt ------------
__global__ void k_mega1(const __half* __restrict__ ft, const float* __restrict__ lam,
                        float* __restrict__ out, float* __restrict__ out2) {
    __shared__ float s_att[8][128];
    __shared__ int s_src[8][128];
    int wslot = threadIdx.x >> 5;
    int w = (blockIdx.x * blockDim.x + threadIdx.x) >> 5;
    int lane = threadIdx.x & 31;
    if (w >= NN) return;
    int deg = g_cnt[w];
    int st = g_off[w];
    float lamv = lam[0];
    float er = g_er[w];

    float2 acc = make_float2(0.f, 0.f);

    if (deg <= 128) {
        float sc[4];
        float mx = -1e30f;
#pragma unroll
        for (int k = 0; k < 4; k++) {
            int j = lane + 32 * k;
            if (j < deg) {
                int2 ed = g_edge[st + j];
                int s = ed.x;
                s_src[wslot][j] = s;
                float v = g_el[s] + er + lamv * __int_as_float(ed.y);
                v = v > 0.f ? v : 0.2f * v;
                sc[k] = v;
                mx = fmaxf(mx, v);
            }
        }
#pragma unroll
        for (int off = 16; off > 0; off >>= 1)
            mx = fmaxf(mx, __shfl_xor_sync(0xffffffffu, mx, off));
        float sm = 0.f;
#pragma unroll
        for (int k = 0; k < 4; k++) {
            int j = lane + 32 * k;
            if (j < deg) { sc[k] = __expf(sc[k] - mx); sm += sc[k]; }
        }
#pragma unroll
        for (int off = 16; off > 0; off >>= 1)
            sm += __shfl_xor_sync(0xffffffffu, sm, off);
        float rinv = 1.f / sm;
#pragma unroll
        for (int k = 0; k < 4; k++) {
            int j = lane + 32 * k;
            if (j < deg) s_att[wslot][j] = sc[k];
        }
        __syncwarp();
#pragma unroll 4
        for (int j = 0; j < deg; j++) {
            float a = s_att[wslot][j] * rinv;
            int s = s_src[wslot][j];
            float2 f = __half22float2(*(const __half2*)&ft[s * 64 + lane * 2]);
            acc.x = fmaf(f.x, a, acc.x);
            acc.y = fmaf(f.y, a, acc.y);
        }
    } else {
        float mx = -1e30f;
        for (int j = lane; j < deg; j += 32) {
            int p = st + j;
            int2 ed = g_edge[p];
            float v = g_el[ed.x] + er + lamv * __int_as_float(ed.y);
            v = v > 0.f ? v : 0.2f * v;
            g_att[p] = v;
            mx = fmaxf(mx, v);
        }
#pragma unroll
        for (int off = 16; off > 0; off >>= 1)
            mx = fmaxf(mx, __shfl_xor_sync(0xffffffffu, mx, off));
        float sm = 0.f;
        for (int j = lane; j < deg; j += 32) {
            int p = st + j;
            float v = __expf(g_att[p] - mx);
            g_att[p] = v;
            sm += v;
        }
#pragma unroll
        for (int off = 16; off > 0; off >>= 1)
            sm += __shfl_xor_sync(0xffffffffu, sm, off);
        float rinv = 1.f / sm;
        __syncwarp();
        for (int j = 0; j < deg; j++) {
            int p = st + j;
            int s = g_edge[p].x;
            float a = g_att[p] * rinv;
            float2 f = __half22float2(*(const __half2*)&ft[s * 64 + lane * 2]);
            acc.x = fmaf(f.x, a, acc.x);
            acc.y = fmaf(f.y, a, acc.y);
        }
    }
    *(float2*)&out[w * 64 + lane * 2] = acc;
    if (out2) *(float2*)&out2[w * 64 + lane * 2] = acc;
    if (lane == 0) g_cnt[w] = 0;
}

// ------------------------------- launch --------------------------------------
extern "C" void kernel_launch(void* const* d_in, const int* in_sizes, int n_in,
                              void* d_out, int out_size) {
    (void)in_sizes; (void)n_in;
    const float* feat = (const float*)d_in[0];
    const float* ew   = (const float*)d_in[1];
    const int*   src  = (const int*)d_in[2];
    const int*   dst  = (const int*)d_in[3];
    const float* W0   = (const float*)d_in[4];
    const float* al0  = (const float*)d_in[5];
    const float* ar0  = (const float*)d_in[6];
    const float* lam0 = (const float*)d_in[7];
    const float* W1   = (const float*)d_in[8];
    const float* al1  = (const float*)d_in[9];
    const float* ar1  = (const float*)d_in[10];
    const float* lam1 = (const float*)d_in[11];
    const float* W2   = (const float*)d_in[12];
    const float* al2  = (const float*)d_in[13];
    const float* ar2  = (const float*)d_in[14];
    const float* lam2 = (const float*)d_in[15];
    const float* g0   = (const float*)d_in[16];
    const float* b0   = (const float*)d_in[17];
    const float* g1   = (const float*)d_in[18];
    const float* b1   = (const float*)d_in[19];

    float* out = (float*)d_out;
    float* out2 = (out_size >= 2 * NN * OUTD) ? out + NN * OUTD : nullptr;

    __half* fthp = nullptr;
    float *h1p = nullptr, *h2p = nullptr;
    cudaGetSymbolAddress((void**)&fthp, g_fth);
    cudaGetSymbolAddress((void**)&h1p, g_h1);
    cudaGetSymbolAddress((void**)&h2p, g_h2);

    const int eb = (EE + 255) / 256;
    const int nwb = (NN + 7) / 8;
    const int g128b = (NN + 63) / 64;
    const int g64b = (NN + 127) / 128;

    const int smem128 = (2 * (64 * 36) + 2 * (32 * 136)) * 4;   // 53248
    const int smem64  = (2 * (128 * 36) + 2 * (32 * 72)) * 4;   // 55296
    cudaFuncSetAttribute(k_gemm_tf32<128>, cudaFuncAttributeMaxDynamicSharedMemorySize, smem128);
    cudaFuncSetAttribute(k_gemm_tf32<64>, cudaFuncAttributeMaxDynamicSharedMemorySize, smem64);

    // CSR by dst
    k_hist<<<eb, 256>>>(dst);
    k_scan_all<<<1, 1024>>>();
    k_scatter<<<eb, 256>>>(src, dst, ew);

    // layer 0
    k_gemm_tf32<128><<<g128b, 256, smem128>>>(feat, W0, fthp, al0, ar0);
    k_mega4<<<nwb, 256>>>(fthp, lam0, feat, g0, b0, h1p);

    // layer 1
    k_gemm_tf32<128><<<g128b, 256, smem128>>>(h1p, W1, fthp, al1, ar1);
    k_mega4<<<nwb, 256>>>(fthp, lam1, h1p, g1, b1, h2p);

    // layer 2
    k_gemm_tf32<64><<<g64b, 256, smem64>>>(h2p, W2, fthp, al2, ar2);
    k_mega1<<<nwb, 256>>>(fthp, lam2, out, out2);
}